// round 14
// baseline (speedup 1.0000x reference)
#include <cuda_runtime.h>
#include <cstdint>
#include <math.h>

#define Bn 8
#define Nn 1024
#define Dn 1024
#define Hn 4096
#define En 16
#define CAP 80
#define SPLITK 4

#define NT 256      // block tile N
#define KT 32       // block tile K
#define STAGES 4
#define CONS_T 320  // 10 consumer warps (5M x 2N, warp tile 16x128)
#define PROD_T 128  // 4 producer warps
#define THREADS (CONS_T + PROD_T)

// stage layout (u32 units):
//   AH [80][20] k-pair u32, row stride 20 (ldmatrix conflict-free) = 1600
//   AL [80][20]                                                    = 1600
//   BH [32 k][128 u32] (256 n bf16, 16B-chunk ^ (k&7) swizzle)     = 4096
//   BL [32][128]                                                   = 4096
#define APS 20
#define OFF_AH 0
#define OFF_AL 1600
#define OFF_BH 3200
#define OFF_BL 7296
#define STAGE_U32 11392
#define MB_OFF_U32 (STAGES * STAGE_U32)              // 45568
#define SMEM_BYTES (MB_OFF_U32 * 4 + 128)            // 182400

// zero-fill bookkeeping (out rows >= CAP, done by gemm1 producers)
#define ZF4_PER_B 241664      // 944*1024/4 float4 per batch zero region
#define OF4_PER_B 262144      // 1024*1024/4 float4 per batch in out
#define ZF4_SKIP  20480       // 80*1024/4 float4 (rows < CAP)
#define ZF4_PER_CTA 15104     // 128 CTAs * 15104 = 1,933,312 = 8*ZF4_PER_B

__device__ float g_hidden[(size_t)Bn * CAP * Hn];
__device__ float g_partial[(size_t)SPLITK * Bn * CAP * Dn];

__device__ __forceinline__ float gelu_exact(float x) {
    return 0.5f * x * (1.0f + erff(x * 0.70710678118654752440f));
}
__device__ __forceinline__ uint32_t smem_u32(const void* p) {
    uint32_t a;
    asm("{ .reg .u64 t; cvta.to.shared.u64 t, %1; cvt.u32.u64 %0, t; }" : "=r"(a) : "l"(p));
    return a;
}
__device__ __forceinline__ void split2(float x, float y, uint32_t& hi, uint32_t& lo) {
    uint32_t bx = __float_as_uint(x), by = __float_as_uint(y);
    asm("prmt.b32 %0, %1, %2, 0x7632;" : "=r"(hi) : "r"(bx), "r"(by));
    float lx = x - __uint_as_float(bx & 0xFFFF0000u);
    float ly = y - __uint_as_float(by & 0xFFFF0000u);
    asm("cvt.rn.bf16x2.f32 %0, %1, %2;" : "=r"(lo) : "f"(ly), "f"(lx));
}
__device__ __forceinline__ void mma_bf16(
    float* acc, uint32_t a0, uint32_t a1, uint32_t a2, uint32_t a3,
    uint32_t b0, uint32_t b1)
{
    asm volatile(
        "mma.sync.aligned.m16n8k16.row.col.f32.bf16.bf16.f32 "
        "{%0,%1,%2,%3}, {%4,%5,%6,%7}, {%8,%9}, {%0,%1,%2,%3};"
        : "+f"(acc[0]), "+f"(acc[1]), "+f"(acc[2]), "+f"(acc[3])
        : "r"(a0), "r"(a1), "r"(a2), "r"(a3), "r"(b0), "r"(b1));
}
#define LDSM_X4(r0, r1, r2, r3, addr) \
    asm volatile("ldmatrix.sync.aligned.m8n8.x4.shared.b16 {%0,%1,%2,%3}, [%4];" \
        : "=r"(r0), "=r"(r1), "=r"(r2), "=r"(r3) : "r"(addr))
#define LDSM_X4T(r0, r1, r2, r3, addr) \
    asm volatile("ldmatrix.sync.aligned.m8n8.x4.trans.shared.b16 {%0,%1,%2,%3}, [%4];" \
        : "=r"(r0), "=r"(r1), "=r"(r2), "=r"(r3) : "r"(addr))

__device__ __forceinline__ void mbar_init(uint32_t a, uint32_t cnt) {
    asm volatile("mbarrier.init.shared.b64 [%0], %1;" :: "r"(a), "r"(cnt) : "memory");
}
__device__ __forceinline__ void mbar_arrive(uint32_t a) {
    asm volatile("mbarrier.arrive.shared.b64 _, [%0];" :: "r"(a) : "memory");
}
__device__ __forceinline__ void mbar_wait(uint32_t a, uint32_t parity) {
    uint32_t done;
    asm volatile(
        "{\n\t.reg .pred p;\n\t"
        "mbarrier.try_wait.parity.shared.b64 p, [%1], %2;\n\t"
        "selp.b32 %0, 1, 0, p;\n\t}"
        : "=r"(done) : "r"(a), "r"(parity) : "memory");
    while (!done) {
        asm volatile(
            "{\n\t.reg .pred p;\n\t"
            "mbarrier.try_wait.parity.shared.b64 p, [%1], %2, 0x989680;\n\t"
            "selp.b32 %0, 1, 0, p;\n\t}"
            : "=r"(done) : "r"(a), "r"(parity) : "memory");
    }
}

// ---------------------------------------------------------------------------
// Warp-specialized core: Out[0:80, n0:n0+256] = A[80 x K] * B[K x N],
// k in [kbase, kbase+ktiles*32). 3-term bf16-split mma.sync, fp32 accum.
// Consumers: warps 0-9 (5M x 2N, 16x128). Producers: warps 10-13.
// 4-stage mbarrier ring. If ZFILL, producers also stream this CTA's slice of
// zeros into Zout (out rows >= CAP) under the main loop.
// ---------------------------------------------------------------------------
template <bool GELU, bool ZFILL>
__device__ __forceinline__ void gemm_core(
    const float* __restrict__ A, int lda,
    const float* __restrict__ Bg, int ldb,
    int n0, int kbase, int ktiles,
    float* __restrict__ Out, int ldo,
    float* __restrict__ Zout, int cta_lin)
{
    extern __shared__ uint32_t Sm[];
    const uint32_t su = smem_u32(Sm);
    const int tid = threadIdx.x;
    const int wid = tid >> 5;
    const int lid = tid & 31;

    const uint32_t mb = su + MB_OFF_U32 * 4;
    // full[s] = mb + s*8 (count PROD_T); empty[s] = mb + 64 + s*8 (count CONS_T)
    if (tid == 0) {
        #pragma unroll
        for (int s = 0; s < STAGES; s++) {
            mbar_init(mb + s * 8, PROD_T);
            mbar_init(mb + 64 + s * 8, CONS_T);
        }
    }
    __syncthreads();

    if (wid < 10) {
        // ================= CONSUMER =================
        const int wm = wid >> 1;        // 0..4
        const int wn = wid & 1;         // 0..1
        const int g = lid >> 2;
        const int c = lid & 3;

        const int a_row = wm * 16 + (lid & 7) + ((lid >> 3) & 1) * 8;
        const uint32_t a_lds = (uint32_t)(a_row * APS + (lid >> 4) * 4) * 4;
        const int krow = lid & 15;
        uint32_t b_lds[8];
        #pragma unroll
        for (int t = 0; t < 8; t++) {
            int chunk = (wn * 16 + t * 2 + (lid >> 4)) ^ (krow & 7);
            b_lds[t] = (uint32_t)(krow * 512 + chunk * 16);
        }

        float acc[16][4];
        #pragma unroll
        for (int j = 0; j < 16; j++)
            #pragma unroll
            for (int i = 0; i < 4; i++) acc[j][i] = 0.0f;

        int s = 0;
        for (int j = 0; j < ktiles; j++) {
            mbar_wait(mb + s * 8, (uint32_t)((j / STAGES) & 1));
            const uint32_t base = su + (uint32_t)s * (STAGE_U32 * 4);

            #pragma unroll
            for (int q = 0; q < 2; q++) {
                uint32_t ah0, ah1, ah2, ah3, al0, al1, al2, al3;
                LDSM_X4(ah0, ah1, ah2, ah3, base + OFF_AH * 4 + a_lds + q * 32);
                LDSM_X4(al0, al1, al2, al3, base + OFF_AL * 4 + a_lds + q * 32);
                #pragma unroll
                for (int t = 0; t < 8; t++) {
                    uint32_t bh0, bh1, bh2, bh3, bl0, bl1, bl2, bl3;
                    const uint32_t boff = b_lds[t] + q * 8192;
                    LDSM_X4T(bh0, bh1, bh2, bh3, base + OFF_BH * 4 + boff);
                    LDSM_X4T(bl0, bl1, bl2, bl3, base + OFF_BL * 4 + boff);
                    mma_bf16(acc[t * 2 + 0], ah0, ah1, ah2, ah3, bh0, bh1);
                    mma_bf16(acc[t * 2 + 0], ah0, ah1, ah2, ah3, bl0, bl1);
                    mma_bf16(acc[t * 2 + 0], al0, al1, al2, al3, bh0, bh1);
                    mma_bf16(acc[t * 2 + 1], ah0, ah1, ah2, ah3, bh2, bh3);
                    mma_bf16(acc[t * 2 + 1], ah0, ah1, ah2, ah3, bl2, bl3);
                    mma_bf16(acc[t * 2 + 1], al0, al1, al2, al3, bh2, bh3);
                }
            }
            mbar_arrive(mb + 64 + s * 8);
            if (++s == STAGES) s = 0;
        }

        // epilogue: rows all < 80 by construction
        #pragma unroll
        for (int jf = 0; jf < 16; jf++) {
            const int n = n0 + wn * 128 + jf * 8 + 2 * c;
            #pragma unroll
            for (int h = 0; h < 2; h++) {
                const int m = wm * 16 + g + 8 * h;
                float2 v;
                v.x = acc[jf][2 * h + 0];
                v.y = acc[jf][2 * h + 1];
                if (GELU) { v.x = gelu_exact(v.x); v.y = gelu_exact(v.y); }
                *reinterpret_cast<float2*>(&Out[(size_t)m * ldo + n]) = v;
            }
        }
    } else {
        // ================= PRODUCER =================
        const int ptid = tid - CONS_T;   // 0..127
        int s = 0;
        for (int j = 0; j < ktiles; j++) {
            if (j >= STAGES)
                mbar_wait(mb + 64 + s * 8, (uint32_t)((j / STAGES + 1) & 1));
            const int k0 = kbase + j * KT;
            uint32_t* base = Sm + (size_t)s * STAGE_U32;

            // A: 80 rows x 8 f4 = 640 -> 5 per thread
            float4 av[5];
            #pragma unroll
            for (int r = 0; r < 5; r++) {
                int idx = ptid + r * 128;
                av[r] = *reinterpret_cast<const float4*>(
                    &A[(size_t)(idx >> 3) * lda + k0 + (idx & 7) * 4]);
            }
            #pragma unroll
            for (int r = 0; r < 5; r++) {
                int idx = ptid + r * 128;
                uint32_t h0, l0, h1, l1;
                split2(av[r].x, av[r].y, h0, l0);
                split2(av[r].z, av[r].w, h1, l1);
                int d = (idx >> 3) * APS + (idx & 7) * 2;
                *reinterpret_cast<uint2*>(base + OFF_AH + d) = make_uint2(h0, h1);
                *reinterpret_cast<uint2*>(base + OFF_AL + d) = make_uint2(l0, l1);
            }
            // B: 32 k-rows x 64 f4 = 2048 -> 16 per thread, two chunks of 8
            #pragma unroll
            for (int half = 0; half < 2; half++) {
                float4 bv[8];
                #pragma unroll
                for (int r = 0; r < 8; r++) {
                    int idx = ptid + (half * 8 + r) * 128;
                    bv[r] = *reinterpret_cast<const float4*>(
                        &Bg[(size_t)(k0 + (idx >> 6)) * ldb + n0 + (idx & 63) * 4]);
                }
                #pragma unroll
                for (int r = 0; r < 8; r++) {
                    int idx = ptid + (half * 8 + r) * 128;
                    int k = idx >> 6, n4 = idx & 63;
                    int d = k * 128 + (((n4 >> 1) ^ (k & 7)) << 2) + (n4 & 1) * 2;
                    uint32_t h0, l0, h1, l1;
                    split2(bv[r].x, bv[r].y, h0, l0);
                    split2(bv[r].z, bv[r].w, h1, l1);
                    *reinterpret_cast<uint2*>(base + OFF_BH + d) = make_uint2(h0, h1);
                    *reinterpret_cast<uint2*>(base + OFF_BL + d) = make_uint2(l0, l1);
                }
            }
            mbar_arrive(mb + s * 8);

            // Stream zero-fill of out rows >= CAP under the main loop.
            if (ZFILL) {
                const float4 z = make_float4(0.f, 0.f, 0.f, 0.f);
                #pragma unroll
                for (int r = 0; r < 4; r++) {
                    int local = j * 512 + r * 128 + ptid;
                    if (local < ZF4_PER_CTA) {
                        int zi = cta_lin * ZF4_PER_CTA + local;
                        int b = zi / ZF4_PER_B;
                        int off = zi - b * ZF4_PER_B;
                        reinterpret_cast<float4*>(Zout)
                            [(size_t)b * OF4_PER_B + ZF4_SKIP + off] = z;
                    }
                }
            }
            if (++s == STAGES) s = 0;
        }
    }
}

__global__ __launch_bounds__(THREADS, 1)
void gemm1_kernel(const float* __restrict__ inputs, const int* __restrict__ y,
                  const float* __restrict__ w1, float* __restrict__ out)
{
    const int b = blockIdx.y;
    const int e = y[b] % En;
    const int cta_lin = blockIdx.y * (Hn / NT) + blockIdx.x;   // 0..127
    gemm_core<true, true>(inputs + (size_t)b * Nn * Dn, Dn,
                          w1 + (size_t)e * Dn * Hn, Hn,
                          blockIdx.x * NT, 0, Dn / KT,
                          g_hidden + (size_t)b * CAP * Hn, Hn,
                          out, cta_lin);
}

__global__ __launch_bounds__(THREADS, 1)
void gemm2_kernel(const int* __restrict__ y, const float* __restrict__ w2)
{
    const int b = blockIdx.y;
    const int e = y[b] % En;
    const int split = blockIdx.z;
    gemm_core<false, false>(g_hidden + (size_t)b * CAP * Hn, Hn,
                            w2 + (size_t)e * Hn * Dn, Dn,
                            blockIdx.x * NT, split * (Hn / SPLITK), (Hn / SPLITK) / KT,
                            g_partial + ((size_t)split * Bn + b) * CAP * Dn, Dn,
                            nullptr, 0);
}

// Sum split-K partials into out for tokens < CAP only
// (rows >= CAP already zeroed by gemm1's producers).
__global__ __launch_bounds__(256) void reduce_kernel(float* __restrict__ out)
{
    const size_t idx4 = (size_t)blockIdx.x * blockDim.x + threadIdx.x;
    const size_t total4 = (size_t)Bn * CAP * Dn / 4;      // 163840
    if (idx4 >= total4) return;
    const int per_b4 = CAP * Dn / 4;
    const int b = (int)(idx4 / per_b4);
    const int r = (int)(idx4 % per_b4);
    const int tok = r / (Dn / 4);
    const int d4 = r % (Dn / 4);

    float4 v = make_float4(0.f, 0.f, 0.f, 0.f);
    #pragma unroll
    for (int s = 0; s < SPLITK; s++) {
        const float4 p = *reinterpret_cast<const float4*>(
            &g_partial[(((size_t)s * Bn + b) * CAP + tok) * Dn + d4 * 4]);
        v.x += p.x; v.y += p.y; v.z += p.z; v.w += p.w;
    }
    *reinterpret_cast<float4*>(&out[((size_t)b * Nn + tok) * Dn + d4 * 4]) = v;
}

extern "C" void kernel_launch(void* const* d_in, const int* in_sizes, int n_in,
                              void* d_out, int out_size) {
    const float* inputs = (const float*)d_in[0];   // (8, 1024, 1024) f32
    const int*   y      = (const int*)d_in[1];     // (8,) i32
    const float* w1     = (const float*)d_in[2];   // (16, 1024, 4096) f32
    const float* w2     = (const float*)d_in[3];   // (16, 4096, 1024) f32
    float* out = (float*)d_out;                    // (8, 1024, 1024) f32

    cudaFuncSetAttribute(gemm1_kernel, cudaFuncAttributeMaxDynamicSharedMemorySize, SMEM_BYTES);
    cudaFuncSetAttribute(gemm2_kernel, cudaFuncAttributeMaxDynamicSharedMemorySize, SMEM_BYTES);

    dim3 g1(Hn / NT, Bn);              // 16 x 8 = 128 CTAs (one wave)
    gemm1_kernel<<<g1, THREADS, SMEM_BYTES>>>(inputs, y, w1, out);

    dim3 g2(Dn / NT, Bn, SPLITK);      // 4 x 8 x 4 = 128 CTAs
    gemm2_kernel<<<g2, THREADS, SMEM_BYTES>>>(y, w2);

    const size_t total4 = (size_t)Bn * CAP * Dn / 4;
    reduce_kernel<<<(unsigned)((total4 + 255) / 256), 256>>>(out);
}

// round 15
// speedup vs baseline: 1.0438x; 1.0438x over previous
#include <cuda_runtime.h>
#include <cstdint>
#include <math.h>

#define Bn 8
#define Nn 1024
#define Dn 1024
#define Hn 4096
#define En 16
#define CAP 80
#define SPLITK 4

#define NT 256      // block tile N
#define KT 32       // block tile K
#define STAGES 4
#define CONS_T 320  // 10 consumer warps (5M x 2N, warp tile 16x128)
#define PROD_T 128  // 4 producer warps
#define THREADS (CONS_T + PROD_T)

// stage layout (u32 units):
//   AH [80][20] k-pair u32, row stride 20 (ldmatrix conflict-free) = 1600
//   AL [80][20]                                                    = 1600
//   BH [32 k][128 u32] (256 n bf16, 16B-chunk ^ (k&7) swizzle)     = 4096
//   BL [32][128]                                                   = 4096
#define APS 20
#define OFF_AH 0
#define OFF_AL 1600
#define OFF_BH 3200
#define OFF_BL 7296
#define STAGE_U32 11392
#define MB_OFF_U32 (STAGES * STAGE_U32)              // 45568
#define SMEM_BYTES (MB_OFF_U32 * 4 + 128)            // 182400

// zero-fill bookkeeping (out rows >= CAP, streamed by gemm2 consumers)
#define ZF4_PER_B 241664      // 944*1024/4 float4 per batch zero region
#define OF4_PER_B 262144      // 1024*1024/4 float4 per batch in out
#define ZF4_SKIP  20480       // 80*1024/4 float4 (rows < CAP)
#define ZF4_PER_CTA 15104     // 128 CTAs * 15104 = 1,933,312 = 8*ZF4_PER_B

__device__ float g_hidden[(size_t)Bn * CAP * Hn];
__device__ float g_partial[(size_t)SPLITK * Bn * CAP * Dn];

__device__ __forceinline__ float gelu_exact(float x) {
    return 0.5f * x * (1.0f + erff(x * 0.70710678118654752440f));
}
__device__ __forceinline__ uint32_t smem_u32(const void* p) {
    uint32_t a;
    asm("{ .reg .u64 t; cvta.to.shared.u64 t, %1; cvt.u32.u64 %0, t; }" : "=r"(a) : "l"(p));
    return a;
}
__device__ __forceinline__ void split2(float x, float y, uint32_t& hi, uint32_t& lo) {
    uint32_t bx = __float_as_uint(x), by = __float_as_uint(y);
    asm("prmt.b32 %0, %1, %2, 0x7632;" : "=r"(hi) : "r"(bx), "r"(by));
    float lx = x - __uint_as_float(bx & 0xFFFF0000u);
    float ly = y - __uint_as_float(by & 0xFFFF0000u);
    asm("cvt.rn.bf16x2.f32 %0, %1, %2;" : "=r"(lo) : "f"(ly), "f"(lx));
}
__device__ __forceinline__ void mma_bf16(
    float* acc, uint32_t a0, uint32_t a1, uint32_t a2, uint32_t a3,
    uint32_t b0, uint32_t b1)
{
    asm volatile(
        "mma.sync.aligned.m16n8k16.row.col.f32.bf16.bf16.f32 "
        "{%0,%1,%2,%3}, {%4,%5,%6,%7}, {%8,%9}, {%0,%1,%2,%3};"
        : "+f"(acc[0]), "+f"(acc[1]), "+f"(acc[2]), "+f"(acc[3])
        : "r"(a0), "r"(a1), "r"(a2), "r"(a3), "r"(b0), "r"(b1));
}
#define LDSM_X4(r0, r1, r2, r3, addr) \
    asm volatile("ldmatrix.sync.aligned.m8n8.x4.shared.b16 {%0,%1,%2,%3}, [%4];" \
        : "=r"(r0), "=r"(r1), "=r"(r2), "=r"(r3) : "r"(addr))
#define LDSM_X4T(r0, r1, r2, r3, addr) \
    asm volatile("ldmatrix.sync.aligned.m8n8.x4.trans.shared.b16 {%0,%1,%2,%3}, [%4];" \
        : "=r"(r0), "=r"(r1), "=r"(r2), "=r"(r3) : "r"(addr))

__device__ __forceinline__ void mbar_init(uint32_t a, uint32_t cnt) {
    asm volatile("mbarrier.init.shared.b64 [%0], %1;" :: "r"(a), "r"(cnt) : "memory");
}
__device__ __forceinline__ void mbar_arrive(uint32_t a) {
    asm volatile("mbarrier.arrive.shared.b64 _, [%0];" :: "r"(a) : "memory");
}
__device__ __forceinline__ void mbar_wait(uint32_t a, uint32_t parity) {
    uint32_t done;
    asm volatile(
        "{\n\t.reg .pred p;\n\t"
        "mbarrier.try_wait.parity.shared.b64 p, [%1], %2;\n\t"
        "selp.b32 %0, 1, 0, p;\n\t}"
        : "=r"(done) : "r"(a), "r"(parity) : "memory");
    while (!done) {
        asm volatile(
            "{\n\t.reg .pred p;\n\t"
            "mbarrier.try_wait.parity.shared.b64 p, [%1], %2, 0x989680;\n\t"
            "selp.b32 %0, 1, 0, p;\n\t}"
            : "=r"(done) : "r"(a), "r"(parity) : "memory");
    }
}

// ---------------------------------------------------------------------------
// Warp-specialized core: Out[0:80, n0:n0+256] = A[80 x K] * B[K x N],
// k in [kbase, kbase+ktiles*32). 3-term bf16-split mma.sync, fp32 accum.
// Consumers: warps 0-9 (5M x 2N, 16x128). Producers: warps 10-13.
// 4-stage mbarrier ring. If ZFILL, CONSUMERS stream this CTA's slice of
// zeros into Zout (out rows >= CAP) during their idle prologue window.
// ---------------------------------------------------------------------------
template <bool GELU, bool ZFILL>
__device__ __forceinline__ void gemm_core(
    const float* __restrict__ A, int lda,
    const float* __restrict__ Bg, int ldb,
    int n0, int kbase, int ktiles,
    float* __restrict__ Out, int ldo,
    float* __restrict__ Zout, int cta_lin)
{
    extern __shared__ uint32_t Sm[];
    const uint32_t su = smem_u32(Sm);
    const int tid = threadIdx.x;
    const int wid = tid >> 5;
    const int lid = tid & 31;

    const uint32_t mb = su + MB_OFF_U32 * 4;
    // full[s] = mb + s*8 (count PROD_T); empty[s] = mb + 64 + s*8 (count CONS_T)
    if (tid == 0) {
        #pragma unroll
        for (int s = 0; s < STAGES; s++) {
            mbar_init(mb + s * 8, PROD_T);
            mbar_init(mb + 64 + s * 8, CONS_T);
        }
    }
    __syncthreads();

    if (wid < 10) {
        // ================= CONSUMER =================
        const int wm = wid >> 1;        // 0..4
        const int wn = wid & 1;         // 0..1
        const int g = lid >> 2;
        const int c = lid & 3;

        // Zero-fill out rows >= CAP while waiting for the first stage:
        // fire-and-forget STGs issued in the otherwise-idle prologue.
        if (ZFILL) {
            const float4 z = make_float4(0.f, 0.f, 0.f, 0.f);
            const int zbase = cta_lin * ZF4_PER_CTA;
            #pragma unroll 4
            for (int r = 0; r < 48; r++) {
                int local = r * CONS_T + tid;
                if (local < ZF4_PER_CTA) {
                    int zi = zbase + local;
                    int b = zi / ZF4_PER_B;
                    int off = zi - b * ZF4_PER_B;
                    reinterpret_cast<float4*>(Zout)
                        [(size_t)b * OF4_PER_B + ZF4_SKIP + off] = z;
                }
            }
        }

        const int a_row = wm * 16 + (lid & 7) + ((lid >> 3) & 1) * 8;
        const uint32_t a_lds = (uint32_t)(a_row * APS + (lid >> 4) * 4) * 4;
        const int krow = lid & 15;
        uint32_t b_lds[8];
        #pragma unroll
        for (int t = 0; t < 8; t++) {
            int chunk = (wn * 16 + t * 2 + (lid >> 4)) ^ (krow & 7);
            b_lds[t] = (uint32_t)(krow * 512 + chunk * 16);
        }

        float acc[16][4];
        #pragma unroll
        for (int j = 0; j < 16; j++)
            #pragma unroll
            for (int i = 0; i < 4; i++) acc[j][i] = 0.0f;

        int s = 0;
        for (int j = 0; j < ktiles; j++) {
            mbar_wait(mb + s * 8, (uint32_t)((j / STAGES) & 1));
            const uint32_t base = su + (uint32_t)s * (STAGE_U32 * 4);

            #pragma unroll
            for (int q = 0; q < 2; q++) {
                uint32_t ah0, ah1, ah2, ah3, al0, al1, al2, al3;
                LDSM_X4(ah0, ah1, ah2, ah3, base + OFF_AH * 4 + a_lds + q * 32);
                LDSM_X4(al0, al1, al2, al3, base + OFF_AL * 4 + a_lds + q * 32);
                #pragma unroll
                for (int t = 0; t < 8; t++) {
                    uint32_t bh0, bh1, bh2, bh3, bl0, bl1, bl2, bl3;
                    const uint32_t boff = b_lds[t] + q * 8192;
                    LDSM_X4T(bh0, bh1, bh2, bh3, base + OFF_BH * 4 + boff);
                    LDSM_X4T(bl0, bl1, bl2, bl3, base + OFF_BL * 4 + boff);
                    mma_bf16(acc[t * 2 + 0], ah0, ah1, ah2, ah3, bh0, bh1);
                    mma_bf16(acc[t * 2 + 0], ah0, ah1, ah2, ah3, bl0, bl1);
                    mma_bf16(acc[t * 2 + 0], al0, al1, al2, al3, bh0, bh1);
                    mma_bf16(acc[t * 2 + 1], ah0, ah1, ah2, ah3, bh2, bh3);
                    mma_bf16(acc[t * 2 + 1], ah0, ah1, ah2, ah3, bl2, bl3);
                    mma_bf16(acc[t * 2 + 1], al0, al1, al2, al3, bh2, bh3);
                }
            }
            mbar_arrive(mb + 64 + s * 8);
            if (++s == STAGES) s = 0;
        }

        // epilogue: rows all < 80 by construction
        #pragma unroll
        for (int jf = 0; jf < 16; jf++) {
            const int n = n0 + wn * 128 + jf * 8 + 2 * c;
            #pragma unroll
            for (int h = 0; h < 2; h++) {
                const int m = wm * 16 + g + 8 * h;
                float2 v;
                v.x = acc[jf][2 * h + 0];
                v.y = acc[jf][2 * h + 1];
                if (GELU) { v.x = gelu_exact(v.x); v.y = gelu_exact(v.y); }
                *reinterpret_cast<float2*>(&Out[(size_t)m * ldo + n]) = v;
            }
        }
    } else {
        // ================= PRODUCER =================
        const int ptid = tid - CONS_T;   // 0..127
        int s = 0;
        for (int j = 0; j < ktiles; j++) {
            if (j >= STAGES)
                mbar_wait(mb + 64 + s * 8, (uint32_t)((j / STAGES + 1) & 1));
            const int k0 = kbase + j * KT;
            uint32_t* base = Sm + (size_t)s * STAGE_U32;

            // A: 80 rows x 8 f4 = 640 -> 5 per thread
            float4 av[5];
            #pragma unroll
            for (int r = 0; r < 5; r++) {
                int idx = ptid + r * 128;
                av[r] = *reinterpret_cast<const float4*>(
                    &A[(size_t)(idx >> 3) * lda + k0 + (idx & 7) * 4]);
            }
            #pragma unroll
            for (int r = 0; r < 5; r++) {
                int idx = ptid + r * 128;
                uint32_t h0, l0, h1, l1;
                split2(av[r].x, av[r].y, h0, l0);
                split2(av[r].z, av[r].w, h1, l1);
                int d = (idx >> 3) * APS + (idx & 7) * 2;
                *reinterpret_cast<uint2*>(base + OFF_AH + d) = make_uint2(h0, h1);
                *reinterpret_cast<uint2*>(base + OFF_AL + d) = make_uint2(l0, l1);
            }
            // B: 32 k-rows x 64 f4 = 2048 -> 16 per thread, two chunks of 8
            #pragma unroll
            for (int half = 0; half < 2; half++) {
                float4 bv[8];
                #pragma unroll
                for (int r = 0; r < 8; r++) {
                    int idx = ptid + (half * 8 + r) * 128;
                    bv[r] = *reinterpret_cast<const float4*>(
                        &Bg[(size_t)(k0 + (idx >> 6)) * ldb + n0 + (idx & 63) * 4]);
                }
                #pragma unroll
                for (int r = 0; r < 8; r++) {
                    int idx = ptid + (half * 8 + r) * 128;
                    int k = idx >> 6, n4 = idx & 63;
                    int d = k * 128 + (((n4 >> 1) ^ (k & 7)) << 2) + (n4 & 1) * 2;
                    uint32_t h0, l0, h1, l1;
                    split2(bv[r].x, bv[r].y, h0, l0);
                    split2(bv[r].z, bv[r].w, h1, l1);
                    *reinterpret_cast<uint2*>(base + OFF_BH + d) = make_uint2(h0, h1);
                    *reinterpret_cast<uint2*>(base + OFF_BL + d) = make_uint2(l0, l1);
                }
            }
            mbar_arrive(mb + s * 8);
            if (++s == STAGES) s = 0;
        }
    }
}

__global__ __launch_bounds__(THREADS, 1)
void gemm1_kernel(const float* __restrict__ inputs, const int* __restrict__ y,
                  const float* __restrict__ w1)
{
    const int b = blockIdx.y;
    const int e = y[b] % En;
    gemm_core<true, false>(inputs + (size_t)b * Nn * Dn, Dn,
                           w1 + (size_t)e * Dn * Hn, Hn,
                           blockIdx.x * NT, 0, Dn / KT,
                           g_hidden + (size_t)b * CAP * Hn, Hn,
                           nullptr, 0);
}

__global__ __launch_bounds__(THREADS, 1)
void gemm2_kernel(const int* __restrict__ y, const float* __restrict__ w2,
                  float* __restrict__ out)
{
    const int b = blockIdx.y;
    const int e = y[b] % En;
    const int split = blockIdx.z;
    const int cta_lin = (blockIdx.z * Bn + blockIdx.y) * (Dn / NT) + blockIdx.x; // 0..127
    gemm_core<false, true>(g_hidden + (size_t)b * CAP * Hn, Hn,
                           w2 + (size_t)e * Hn * Dn, Dn,
                           blockIdx.x * NT, split * (Hn / SPLITK), (Hn / SPLITK) / KT,
                           g_partial + ((size_t)split * Bn + b) * CAP * Dn, Dn,
                           out, cta_lin);
}

// Sum split-K partials into out for tokens < CAP only
// (rows >= CAP already zeroed by gemm2's consumers).
__global__ __launch_bounds__(256) void reduce_kernel(float* __restrict__ out)
{
    const size_t idx4 = (size_t)blockIdx.x * blockDim.x + threadIdx.x;
    const size_t total4 = (size_t)Bn * CAP * Dn / 4;      // 163840
    if (idx4 >= total4) return;
    const int per_b4 = CAP * Dn / 4;
    const int b = (int)(idx4 / per_b4);
    const int r = (int)(idx4 % per_b4);
    const int tok = r / (Dn / 4);
    const int d4 = r % (Dn / 4);

    float4 v = make_float4(0.f, 0.f, 0.f, 0.f);
    #pragma unroll
    for (int s = 0; s < SPLITK; s++) {
        const float4 p = *reinterpret_cast<const float4*>(
            &g_partial[(((size_t)s * Bn + b) * CAP + tok) * Dn + d4 * 4]);
        v.x += p.x; v.y += p.y; v.z += p.z; v.w += p.w;
    }
    *reinterpret_cast<float4*>(&out[((size_t)b * Nn + tok) * Dn + d4 * 4]) = v;
}

extern "C" void kernel_launch(void* const* d_in, const int* in_sizes, int n_in,
                              void* d_out, int out_size) {
    const float* inputs = (const float*)d_in[0];   // (8, 1024, 1024) f32
    const int*   y      = (const int*)d_in[1];     // (8,) i32
    const float* w1     = (const float*)d_in[2];   // (16, 1024, 4096) f32
    const float* w2     = (const float*)d_in[3];   // (16, 4096, 1024) f32
    float* out = (float*)d_out;                    // (8, 1024, 1024) f32

    cudaFuncSetAttribute(gemm1_kernel, cudaFuncAttributeMaxDynamicSharedMemorySize, SMEM_BYTES);
    cudaFuncSetAttribute(gemm2_kernel, cudaFuncAttributeMaxDynamicSharedMemorySize, SMEM_BYTES);

    dim3 g1(Hn / NT, Bn);              // 16 x 8 = 128 CTAs (one wave)
    gemm1_kernel<<<g1, THREADS, SMEM_BYTES>>>(inputs, y, w1);

    dim3 g2(Dn / NT, Bn, SPLITK);      // 4 x 8 x 4 = 128 CTAs
    gemm2_kernel<<<g2, THREADS, SMEM_BYTES>>>(y, w2, out);

    const size_t total4 = (size_t)Bn * CAP * Dn / 4;
    reduce_kernel<<<(unsigned)((total4 + 255) / 256), 256>>>(out);
}